// round 5
// baseline (speedup 1.0000x reference)
#include <cuda_runtime.h>
#include <math.h>

#define N_NODES 50000
#define N_EDGES 800000
#define NB      64
#define IN_DIM  64
#define HID     128
#define OUT_DIM 64

// ---------------- scratch (device globals: no allocs allowed) ----------------
__device__ __align__(16) float g_deg[N_NODES];
__device__ __align__(16) float g_dis[N_NODES];
__device__ __align__(16) float g_bufA[(size_t)N_NODES * HID];  // GEMM outputs / layer-2 agg source
__device__ __align__(16) float g_bufB[(size_t)N_NODES * HID];  // aggregation target / GEMM input
__device__ __align__(16) float g_pooled[NB * HID];
__device__ __align__(16) float g_cnt[NB];

// ---------------- init: deg=1 (self loops), pooled=0, cnt=0 ----------------
__global__ void k_init() {
    int i = blockIdx.x * blockDim.x + threadIdx.x;
    if (i < N_NODES) g_deg[i] = 1.0f;
    if (i < NB * HID) g_pooled[i] = 0.0f;
    if (i < NB) g_cnt[i] = 0.0f;
}

// ---------------- degree accumulation over dst (int32 indices!) ----------------
__global__ void k_deg(const int* __restrict__ dst) {
    int e = blockIdx.x * blockDim.x + threadIdx.x;
    if (e < N_EDGES) atomicAdd(&g_deg[dst[e]], 1.0f);
}

__global__ void k_dis() {
    int i = blockIdx.x * blockDim.x + threadIdx.x;
    if (i < N_NODES) g_dis[i] = rsqrtf(g_deg[i]);
}

// ---------------- self-loop init: bufB[i] = feat[i] * dis[i]^2 ----------------
// C4 = columns/4. One thread per float4. FG=true -> feat is g_bufA, else xin param.
template <int C4, bool FG>
__global__ void k_selfinit(const float* __restrict__ xin) {
    int t = blockIdx.x * blockDim.x + threadIdx.x;
    if (t >= N_NODES * C4) return;
    const float* feat = FG ? g_bufA : xin;
    int i = t / C4;
    float d = g_dis[i];
    float w = d * d;
    float4 v = reinterpret_cast<const float4*>(feat)[t];
    v.x *= w; v.y *= w; v.z *= w; v.w *= w;
    reinterpret_cast<float4*>(g_bufB)[t] = v;
}

// ---------------- edge scatter: bufB[dst] += feat[src] * dis[src]*dis[dst] ----------------
template <int C4, bool FG>
__global__ __launch_bounds__(256) void k_scatter(const float* __restrict__ xin,
                                                 const int* __restrict__ src,
                                                 const int* __restrict__ dst) {
    long long t = (long long)blockIdx.x * blockDim.x + threadIdx.x;
    int e = (int)(t / C4);
    int g = (int)(t & (C4 - 1));
    if (e >= N_EDGES) return;
    const float* feat = FG ? g_bufA : xin;
    int s = src[e];
    int d = dst[e];
    float w = g_dis[s] * g_dis[d];
    float4 v = reinterpret_cast<const float4*>(feat)[(long long)s * C4 + g];
    float* ap = g_bufB + ((long long)d * C4 + g) * 4;
    atomicAdd(ap + 0, v.x * w);
    atomicAdd(ap + 1, v.y * w);
    atomicAdd(ap + 2, v.z * w);
    atomicAdd(ap + 3, v.w * w);
}

// ---------------- GEMM: bufA[M x 128] = relu(bufB[M x K] @ W[K x 128] + bias) ----------------
// 128 threads/block, 64 rows/block, each thread owns one output column.
template <int K>
__global__ __launch_bounds__(128) void k_gemm_bias_relu(const float* __restrict__ W,
                                                        const float* __restrict__ bias) {
    constexpr int K4 = K / 4;
    __shared__ float4 xs[64 * K4];
    const int tid = threadIdx.x;
    const int row0 = blockIdx.x * 64;

    for (int idx = tid; idx < 64 * K4; idx += 128) {
        int r = idx / K4;
        int q = idx - r * K4;
        int row = row0 + r;
        float4 v = make_float4(0.f, 0.f, 0.f, 0.f);
        if (row < N_NODES) v = reinterpret_cast<const float4*>(g_bufB)[(long long)row * K4 + q];
        xs[idx] = v;
    }
    __syncthreads();

    float acc[64];
#pragma unroll
    for (int r = 0; r < 64; r++) acc[r] = 0.0f;

#pragma unroll 1
    for (int k0 = 0; k0 < K; k0 += 8) {
        float w0 = W[(k0 + 0) * HID + tid];
        float w1 = W[(k0 + 1) * HID + tid];
        float w2 = W[(k0 + 2) * HID + tid];
        float w3 = W[(k0 + 3) * HID + tid];
        float w4 = W[(k0 + 4) * HID + tid];
        float w5 = W[(k0 + 5) * HID + tid];
        float w6 = W[(k0 + 6) * HID + tid];
        float w7 = W[(k0 + 7) * HID + tid];
        int q0 = k0 / 4;
#pragma unroll
        for (int r = 0; r < 64; r++) {
            float4 a = xs[r * K4 + q0];
            float4 b = xs[r * K4 + q0 + 1];
            float s = acc[r];
            s += a.x * w0; s += a.y * w1; s += a.z * w2; s += a.w * w3;
            s += b.x * w4; s += b.y * w5; s += b.z * w6; s += b.w * w7;
            acc[r] = s;
        }
    }

    float bv = bias[tid];
#pragma unroll 1
    for (int r = 0; r < 64; r++) {
        int row = row0 + r;
        if (row < N_NODES) g_bufA[(long long)row * HID + tid] = fmaxf(acc[r] + bv, 0.0f);
    }
}

// ---------------- pooling: pooled[batch[i]] += bufA[i]; cnt[batch[i]] += 1 ----------------
__global__ void k_pool(const int* __restrict__ batch) {
    int t = blockIdx.x * blockDim.x + threadIdx.x;
    int node = t >> 5;
    int lane = t & 31;
    if (node >= N_NODES) return;
    int b = batch[node];
    float4 v = reinterpret_cast<const float4*>(g_bufA)[(long long)node * 32 + lane];
    float* ap = g_pooled + b * HID + lane * 4;
    atomicAdd(ap + 0, v.x);
    atomicAdd(ap + 1, v.y);
    atomicAdd(ap + 2, v.z);
    atomicAdd(ap + 3, v.w);
    if (lane == 0) atomicAdd(&g_cnt[b], 1.0f);
}

// ---------------- head: out = relu(mean @ W3 + b3) @ W4 + b4 ----------------
__global__ __launch_bounds__(128) void k_head(const float* __restrict__ W3,
                                              const float* __restrict__ b3,
                                              const float* __restrict__ W4,
                                              const float* __restrict__ b4,
                                              float* __restrict__ out) {
    __shared__ float mean[HID];
    __shared__ float y[HID];
    int b = blockIdx.x;
    int t = threadIdx.x;
    float c = fmaxf(g_cnt[b], 1.0f);
    mean[t] = g_pooled[b * HID + t] / c;
    __syncthreads();

    float acc = b3[t];
#pragma unroll 8
    for (int k = 0; k < HID; k++) acc += mean[k] * W3[k * HID + t];
    y[t] = fmaxf(acc, 0.0f);
    __syncthreads();

    if (t < OUT_DIM) {
        float acc2 = b4[t];
#pragma unroll 8
        for (int k = 0; k < HID; k++) acc2 += y[k] * W4[k * OUT_DIM + t];
        out[b * OUT_DIM + t] = acc2;
    }
}

// ---------------- launch: kernel launches ONLY, no runtime API calls ----------------
extern "C" void kernel_launch(void* const* d_in, const int* in_sizes, int n_in,
                              void* d_out, int out_size) {
    const float* x     = (const float*)d_in[0];
    const int*   ei    = (const int*)d_in[1];    // int32! (jax x64 disabled)
    const int*   batch = (const int*)d_in[2];    // int32!
    const float* W1 = (const float*)d_in[3];
    const float* b1 = (const float*)d_in[4];
    const float* W2 = (const float*)d_in[5];
    const float* b2 = (const float*)d_in[6];
    const float* W3 = (const float*)d_in[7];
    const float* b3 = (const float*)d_in[8];
    const float* W4 = (const float*)d_in[9];
    const float* b4 = (const float*)d_in[10];
    float* out = (float*)d_out;

    const int* src = ei;
    const int* dst = ei + N_EDGES;

    // norm
    k_init<<<(N_NODES + 255) / 256, 256>>>();
    k_deg<<<(N_EDGES + 255) / 256, 256>>>(dst);
    k_dis<<<(N_NODES + 255) / 256, 256>>>();

    // layer 1: aggregate X first (64 cols), then GEMM:  relu((A_hat X) W1 + b1) -> bufA
    k_selfinit<16, false><<<(N_NODES * 16 + 255) / 256, 256>>>(x);
    k_scatter<16, false><<<(int)(((long long)N_EDGES * 16 + 255) / 256), 256>>>(x, src, dst);
    k_gemm_bias_relu<IN_DIM><<<(N_NODES + 63) / 64, 128>>>(W1, b1);

    // layer 2: aggregate hidden bufA (128 cols) -> bufB, then GEMM -> bufA
    k_selfinit<32, true><<<(N_NODES * 32 + 255) / 256, 256>>>(x);
    k_scatter<32, true><<<(int)(((long long)N_EDGES * 32 + 255) / 256), 256>>>(x, src, dst);
    k_gemm_bias_relu<HID><<<(N_NODES + 63) / 64, 128>>>(W2, b2);

    // pool + head
    k_pool<<<(N_NODES * 32 + 255) / 256, 256>>>(batch);
    k_head<<<NB, 128>>>(W3, b3, W4, b4, out);
}

// round 6
// speedup vs baseline: 1.6718x; 1.6718x over previous
#include <cuda_runtime.h>
#include <math.h>

#define N_NODES 50000
#define N_EDGES 800000
#define NB      64
#define IN_DIM  64
#define HID     128
#define OUT_DIM 64

// ---------------- scratch (device globals: no allocs allowed) ----------------
__device__ __align__(16) float g_deg[N_NODES];
__device__ __align__(16) float g_dis[N_NODES];
__device__ __align__(16) float g_bufA[(size_t)N_NODES * HID];  // GEMM outputs / layer-2 agg source
__device__ __align__(16) float g_bufB[(size_t)N_NODES * HID];  // aggregation target / GEMM input
__device__ __align__(16) float g_pooled[NB * HID];
__device__ __align__(16) float g_cnt[NB];

__device__ __forceinline__ void red_v4(float* ap, float a, float b, float c, float d) {
    asm volatile("red.global.add.v4.f32 [%0], {%1,%2,%3,%4};"
                 :: "l"(ap), "f"(a), "f"(b), "f"(c), "f"(d) : "memory");
}

// ---------------- init: deg=1 (self loops), pooled=0, cnt=0 ----------------
__global__ void k_init() {
    int i = blockIdx.x * blockDim.x + threadIdx.x;
    if (i < N_NODES) g_deg[i] = 1.0f;
    if (i < NB * HID) g_pooled[i] = 0.0f;
    if (i < NB) g_cnt[i] = 0.0f;
}

// ---------------- degree accumulation over dst (int32 indices) ----------------
__global__ void k_deg(const int* __restrict__ dst) {
    int e = blockIdx.x * blockDim.x + threadIdx.x;
    if (e < N_EDGES) atomicAdd(&g_deg[dst[e]], 1.0f);
}

__global__ void k_dis() {
    int i = blockIdx.x * blockDim.x + threadIdx.x;
    if (i < N_NODES) g_dis[i] = rsqrtf(g_deg[i]);
}

// ---------------- self-loop init: bufB[i] = feat[i] * dis[i]^2 ----------------
template <int C4, bool FG>
__global__ void k_selfinit(const float* __restrict__ xin) {
    int t = blockIdx.x * blockDim.x + threadIdx.x;
    if (t >= N_NODES * C4) return;
    const float* feat = FG ? g_bufA : xin;
    int i = t / C4;
    float d = g_dis[i];
    float w = d * d;
    float4 v = reinterpret_cast<const float4*>(feat)[t];
    v.x *= w; v.y *= w; v.z *= w; v.w *= w;
    reinterpret_cast<float4*>(g_bufB)[t] = v;
}

// ---------------- edge scatter: bufB[dst] += feat[src] * dis[src]*dis[dst] ----------------
template <int C4, bool FG>
__global__ __launch_bounds__(256) void k_scatter(const float* __restrict__ xin,
                                                 const int* __restrict__ src,
                                                 const int* __restrict__ dst) {
    long long t = (long long)blockIdx.x * blockDim.x + threadIdx.x;
    int e = (int)(t / C4);
    int g = (int)(t & (C4 - 1));
    if (e >= N_EDGES) return;
    const float* feat = FG ? g_bufA : xin;
    int s = src[e];
    int d = dst[e];
    float w = g_dis[s] * g_dis[d];
    float4 v = reinterpret_cast<const float4*>(feat)[(long long)s * C4 + g];
    float* ap = g_bufB + ((long long)d * C4 + g) * 4;
    red_v4(ap, v.x * w, v.y * w, v.z * w, v.w * w);
}

// ---------------- GEMM: bufA[M x 128] = relu(bufB[M x K] @ W[K x 128] + bias) ----------------
template <int K>
__global__ __launch_bounds__(128) void k_gemm_bias_relu(const float* __restrict__ W,
                                                        const float* __restrict__ bias) {
    constexpr int K4 = K / 4;
    __shared__ float4 xs[64 * K4];
    const int tid = threadIdx.x;
    const int row0 = blockIdx.x * 64;

    for (int idx = tid; idx < 64 * K4; idx += 128) {
        int r = idx / K4;
        int q = idx - r * K4;
        int row = row0 + r;
        float4 v = make_float4(0.f, 0.f, 0.f, 0.f);
        if (row < N_NODES) v = reinterpret_cast<const float4*>(g_bufB)[(long long)row * K4 + q];
        xs[idx] = v;
    }
    __syncthreads();

    float acc[64];
#pragma unroll
    for (int r = 0; r < 64; r++) acc[r] = 0.0f;

#pragma unroll 1
    for (int k0 = 0; k0 < K; k0 += 8) {
        float w0 = W[(k0 + 0) * HID + tid];
        float w1 = W[(k0 + 1) * HID + tid];
        float w2 = W[(k0 + 2) * HID + tid];
        float w3 = W[(k0 + 3) * HID + tid];
        float w4 = W[(k0 + 4) * HID + tid];
        float w5 = W[(k0 + 5) * HID + tid];
        float w6 = W[(k0 + 6) * HID + tid];
        float w7 = W[(k0 + 7) * HID + tid];
        int q0 = k0 / 4;
#pragma unroll
        for (int r = 0; r < 64; r++) {
            float4 a = xs[r * K4 + q0];
            float4 b = xs[r * K4 + q0 + 1];
            float s = acc[r];
            s += a.x * w0; s += a.y * w1; s += a.z * w2; s += a.w * w3;
            s += b.x * w4; s += b.y * w5; s += b.z * w6; s += b.w * w7;
            acc[r] = s;
        }
    }

    float bv = bias[tid];
#pragma unroll 1
    for (int r = 0; r < 64; r++) {
        int row = row0 + r;
        if (row < N_NODES) g_bufA[(long long)row * HID + tid] = fmaxf(acc[r] + bv, 0.0f);
    }
}

// ---------------- pooling: pooled[batch[i]] += bufA[i]; cnt[batch[i]] += 1 ----------------
__global__ void k_pool(const int* __restrict__ batch) {
    int t = blockIdx.x * blockDim.x + threadIdx.x;
    int node = t >> 5;
    int lane = t & 31;
    if (node >= N_NODES) return;
    int b = batch[node];
    float4 v = reinterpret_cast<const float4*>(g_bufA)[(long long)node * 32 + lane];
    float* ap = g_pooled + b * HID + lane * 4;
    red_v4(ap, v.x, v.y, v.z, v.w);
    if (lane == 0) atomicAdd(&g_cnt[b], 1.0f);
}

// ---------------- head: out = relu(mean @ W3 + b3) @ W4 + b4 ----------------
__global__ __launch_bounds__(128) void k_head(const float* __restrict__ W3,
                                              const float* __restrict__ b3,
                                              const float* __restrict__ W4,
                                              const float* __restrict__ b4,
                                              float* __restrict__ out) {
    __shared__ float mean[HID];
    __shared__ float y[HID];
    int b = blockIdx.x;
    int t = threadIdx.x;
    float c = fmaxf(g_cnt[b], 1.0f);
    mean[t] = g_pooled[b * HID + t] / c;
    __syncthreads();

    float acc = b3[t];
#pragma unroll 8
    for (int k = 0; k < HID; k++) acc += mean[k] * W3[k * HID + t];
    y[t] = fmaxf(acc, 0.0f);
    __syncthreads();

    if (t < OUT_DIM) {
        float acc2 = b4[t];
#pragma unroll 8
        for (int k = 0; k < HID; k++) acc2 += y[k] * W4[k * OUT_DIM + t];
        out[b * OUT_DIM + t] = acc2;
    }
}

// ---------------- launch: kernel launches ONLY ----------------
extern "C" void kernel_launch(void* const* d_in, const int* in_sizes, int n_in,
                              void* d_out, int out_size) {
    const float* x     = (const float*)d_in[0];
    const int*   ei    = (const int*)d_in[1];    // int32 (jax x64 disabled)
    const int*   batch = (const int*)d_in[2];
    const float* W1 = (const float*)d_in[3];
    const float* b1 = (const float*)d_in[4];
    const float* W2 = (const float*)d_in[5];
    const float* b2 = (const float*)d_in[6];
    const float* W3 = (const float*)d_in[7];
    const float* b3 = (const float*)d_in[8];
    const float* W4 = (const float*)d_in[9];
    const float* b4 = (const float*)d_in[10];
    float* out = (float*)d_out;

    const int* src = ei;
    const int* dst = ei + N_EDGES;

    // norm
    k_init<<<(N_NODES + 255) / 256, 256>>>();
    k_deg<<<(N_EDGES + 255) / 256, 256>>>(dst);
    k_dis<<<(N_NODES + 255) / 256, 256>>>();

    // layer 1: aggregate X first (64 cols), then GEMM:  relu((A_hat X) W1 + b1) -> bufA
    k_selfinit<16, false><<<(N_NODES * 16 + 255) / 256, 256>>>(x);
    k_scatter<16, false><<<(int)(((long long)N_EDGES * 16 + 255) / 256), 256>>>(x, src, dst);
    k_gemm_bias_relu<IN_DIM><<<(N_NODES + 63) / 64, 128>>>(W1, b1);

    // layer 2: aggregate hidden bufA (128 cols) -> bufB, then GEMM -> bufA
    k_selfinit<32, true><<<(N_NODES * 32 + 255) / 256, 256>>>(x);
    k_scatter<32, true><<<(int)(((long long)N_EDGES * 32 + 255) / 256), 256>>>(x, src, dst);
    k_gemm_bias_relu<HID><<<(N_NODES + 63) / 64, 128>>>(W2, b2);

    // pool + head
    k_pool<<<(N_NODES * 32 + 255) / 256, 256>>>(batch);
    k_head<<<NB, 128>>>(W3, b3, W4, b4, out);
}

// round 7
// speedup vs baseline: 2.0239x; 1.2107x over previous
#include <cuda_runtime.h>
#include <math.h>

#define N_NODES 50000
#define N_EDGES 800000
#define NB      64
#define IN_DIM  64
#define HID     128
#define OUT_DIM 64
#define SCAN_BLOCKS 200   // 200*256 = 51200 >= N_NODES

// ---------------- scratch (device globals: no allocs allowed) ----------------
__device__ __align__(16) int   g_degi[N_NODES];
__device__ __align__(16) float g_dis[N_NODES];
__device__ __align__(16) int   g_rowptr[N_NODES + 1];
__device__ __align__(16) int   g_cursor[N_NODES];
__device__ __align__(16) int   g_csrc[N_EDGES];
__device__ __align__(16) float g_cw[N_EDGES];
__device__ __align__(16) int   g_bsum[256];
__device__ __align__(16) float g_bufA[(size_t)N_NODES * HID];  // GEMM outputs / layer-2 agg source
__device__ __align__(16) float g_bufB[(size_t)N_NODES * HID];  // aggregation target / GEMM input
__device__ __align__(16) float g_pooled[NB * HID];
__device__ __align__(16) float g_cnt[NB];

__device__ __forceinline__ void red_v4(float* ap, float a, float b, float c, float d) {
    asm volatile("red.global.add.v4.f32 [%0], {%1,%2,%3,%4};"
                 :: "l"(ap), "f"(a), "f"(b), "f"(c), "f"(d) : "memory");
}

// ---------------- zero: degi=0, pooled=0, cnt=0 ----------------
__global__ void k_zero() {
    int i = blockIdx.x * blockDim.x + threadIdx.x;
    if (i < N_NODES) g_degi[i] = 0;
    if (i < NB * HID) g_pooled[i] = 0.0f;
    if (i < NB) g_cnt[i] = 0.0f;
}

// ---------------- degree counts over dst ----------------
__global__ void k_deg(const int* __restrict__ dst) {
    int e = blockIdx.x * blockDim.x + threadIdx.x;
    if (e < N_EDGES) atomicAdd(&g_degi[dst[e]], 1);
}

__global__ void k_dis() {
    int i = blockIdx.x * blockDim.x + threadIdx.x;
    if (i < N_NODES) g_dis[i] = rsqrtf((float)(g_degi[i] + 1));  // +1 self loop
}

// ---------------- 2-level exclusive scan of degi -> rowptr ----------------
__global__ __launch_bounds__(256) void k_scan_part() {
    __shared__ int sm[256];
    int b = blockIdx.x, t = threadIdx.x;
    int i = b * 256 + t;
    int v = (i < N_NODES) ? g_degi[i] : 0;
    sm[t] = v;
    __syncthreads();
#pragma unroll
    for (int off = 1; off < 256; off <<= 1) {
        int u = (t >= off) ? sm[t - off] : 0;
        __syncthreads();
        if (t >= off) sm[t] += u;
        __syncthreads();
    }
    if (i < N_NODES) g_rowptr[i] = sm[t] - v;   // block-local exclusive
    if (t == 255) g_bsum[b] = sm[255];
}

__global__ __launch_bounds__(256) void k_scan_top() {
    __shared__ int sm[256];
    int t = threadIdx.x;
    int v = (t < SCAN_BLOCKS) ? g_bsum[t] : 0;
    sm[t] = v;
    __syncthreads();
#pragma unroll
    for (int off = 1; off < 256; off <<= 1) {
        int u = (t >= off) ? sm[t - off] : 0;
        __syncthreads();
        if (t >= off) sm[t] += u;
        __syncthreads();
    }
    if (t < SCAN_BLOCKS) g_bsum[t] = sm[t] - v;  // exclusive block offsets
}

__global__ void k_scan_add() {
    int i = blockIdx.x * blockDim.x + threadIdx.x;
    if (i < N_NODES) {
        int r = g_rowptr[i] + g_bsum[i >> 8];
        g_rowptr[i] = r;
        g_cursor[i] = r;
    }
    if (i == 0) g_rowptr[N_NODES] = N_EDGES;
}

// ---------------- CSR fill: csrc[slot] = src, cw[slot] = dis[s]*dis[d] ----------------
__global__ void k_fill(const int* __restrict__ src, const int* __restrict__ dst) {
    int e = blockIdx.x * blockDim.x + threadIdx.x;
    if (e >= N_EDGES) return;
    int d = dst[e];
    int s = src[e];
    int pos = atomicAdd(&g_cursor[d], 1);
    g_csrc[pos] = s;
    g_cw[pos] = g_dis[s] * g_dis[d];
}

// ---------------- gather, 64-col input (layer 1): warp per node, 2 edges/iter ----------------
__global__ __launch_bounds__(256) void k_gather64(const float* __restrict__ xin) {
    int t = blockIdx.x * blockDim.x + threadIdx.x;
    int node = t >> 5;
    if (node >= N_NODES) return;
    int lane = t & 31;
    int g = lane & 15;
    int h = lane >> 4;
    const float4* feat = reinterpret_cast<const float4*>(xin);

    int beg = g_rowptr[node], end = g_rowptr[node + 1];
    float4 acc = make_float4(0.f, 0.f, 0.f, 0.f);
    for (int i = beg + h; i < end; i += 2) {
        int s = g_csrc[i];
        float w = g_cw[i];
        float4 v = feat[(size_t)s * 16 + g];
        acc.x += v.x * w; acc.y += v.y * w; acc.z += v.z * w; acc.w += v.w * w;
    }
    // combine the two half-warp partial sums
    acc.x += __shfl_xor_sync(0xffffffffu, acc.x, 16);
    acc.y += __shfl_xor_sync(0xffffffffu, acc.y, 16);
    acc.z += __shfl_xor_sync(0xffffffffu, acc.z, 16);
    acc.w += __shfl_xor_sync(0xffffffffu, acc.w, 16);
    if (h == 0) {
        float dd = g_dis[node];
        float w0 = dd * dd;
        float4 sv = feat[(size_t)node * 16 + g];
        acc.x += sv.x * w0; acc.y += sv.y * w0; acc.z += sv.z * w0; acc.w += sv.w * w0;
        reinterpret_cast<float4*>(g_bufB)[(size_t)node * 16 + g] = acc;
    }
}

// ---------------- gather, 128-col hidden (layer 2): warp per node ----------------
__global__ __launch_bounds__(256) void k_gather128() {
    int t = blockIdx.x * blockDim.x + threadIdx.x;
    int node = t >> 5;
    if (node >= N_NODES) return;
    int lane = t & 31;
    const float4* feat = reinterpret_cast<const float4*>(g_bufA);

    int beg = g_rowptr[node], end = g_rowptr[node + 1];
    float dd = g_dis[node];
    float w0 = dd * dd;
    float4 acc = feat[(size_t)node * 32 + lane];
    acc.x *= w0; acc.y *= w0; acc.z *= w0; acc.w *= w0;

    int i = beg;
    for (; i + 2 <= end; i += 2) {
        int s0 = g_csrc[i], s1 = g_csrc[i + 1];
        float wa = g_cw[i], wb = g_cw[i + 1];
        float4 v0 = feat[(size_t)s0 * 32 + lane];
        float4 v1 = feat[(size_t)s1 * 32 + lane];
        acc.x += v0.x * wa + v1.x * wb;
        acc.y += v0.y * wa + v1.y * wb;
        acc.z += v0.z * wa + v1.z * wb;
        acc.w += v0.w * wa + v1.w * wb;
    }
    if (i < end) {
        int s = g_csrc[i];
        float w = g_cw[i];
        float4 v = feat[(size_t)s * 32 + lane];
        acc.x += v.x * w; acc.y += v.y * w; acc.z += v.z * w; acc.w += v.w * w;
    }
    reinterpret_cast<float4*>(g_bufB)[(size_t)node * 32 + lane] = acc;
}

// ---------------- GEMM: bufA[M x 128] = relu(bufB[M x K] @ W[K x 128] + bias) ----------------
template <int K>
__global__ __launch_bounds__(128) void k_gemm_bias_relu(const float* __restrict__ W,
                                                        const float* __restrict__ bias) {
    constexpr int K4 = K / 4;
    __shared__ float4 xs[64 * K4];
    const int tid = threadIdx.x;
    const int row0 = blockIdx.x * 64;

    for (int idx = tid; idx < 64 * K4; idx += 128) {
        int r = idx / K4;
        int q = idx - r * K4;
        int row = row0 + r;
        float4 v = make_float4(0.f, 0.f, 0.f, 0.f);
        if (row < N_NODES) v = reinterpret_cast<const float4*>(g_bufB)[(size_t)row * K4 + q];
        xs[idx] = v;
    }
    __syncthreads();

    float acc[64];
#pragma unroll
    for (int r = 0; r < 64; r++) acc[r] = 0.0f;

#pragma unroll 1
    for (int k0 = 0; k0 < K; k0 += 8) {
        float w0 = W[(k0 + 0) * HID + tid];
        float w1 = W[(k0 + 1) * HID + tid];
        float w2 = W[(k0 + 2) * HID + tid];
        float w3 = W[(k0 + 3) * HID + tid];
        float w4 = W[(k0 + 4) * HID + tid];
        float w5 = W[(k0 + 5) * HID + tid];
        float w6 = W[(k0 + 6) * HID + tid];
        float w7 = W[(k0 + 7) * HID + tid];
        int q0 = k0 / 4;
#pragma unroll
        for (int r = 0; r < 64; r++) {
            float4 a = xs[r * K4 + q0];
            float4 b = xs[r * K4 + q0 + 1];
            float s = acc[r];
            s += a.x * w0; s += a.y * w1; s += a.z * w2; s += a.w * w3;
            s += b.x * w4; s += b.y * w5; s += b.z * w6; s += b.w * w7;
            acc[r] = s;
        }
    }

    float bv = bias[tid];
#pragma unroll 1
    for (int r = 0; r < 64; r++) {
        int row = row0 + r;
        if (row < N_NODES) g_bufA[(size_t)row * HID + tid] = fmaxf(acc[r] + bv, 0.0f);
    }
}

// ---------------- pooling: pooled[batch[i]] += bufA[i]; cnt[batch[i]] += 1 ----------------
__global__ void k_pool(const int* __restrict__ batch) {
    int t = blockIdx.x * blockDim.x + threadIdx.x;
    int node = t >> 5;
    int lane = t & 31;
    if (node >= N_NODES) return;
    int b = batch[node];
    float4 v = reinterpret_cast<const float4*>(g_bufA)[(size_t)node * 32 + lane];
    float* ap = g_pooled + b * HID + lane * 4;
    red_v4(ap, v.x, v.y, v.z, v.w);
    if (lane == 0) atomicAdd(&g_cnt[b], 1.0f);
}

// ---------------- head: out = relu(mean @ W3 + b3) @ W4 + b4 ----------------
__global__ __launch_bounds__(128) void k_head(const float* __restrict__ W3,
                                              const float* __restrict__ b3,
                                              const float* __restrict__ W4,
                                              const float* __restrict__ b4,
                                              float* __restrict__ out) {
    __shared__ float mean[HID];
    __shared__ float y[HID];
    int b = blockIdx.x;
    int t = threadIdx.x;
    float c = fmaxf(g_cnt[b], 1.0f);
    mean[t] = g_pooled[b * HID + t] / c;
    __syncthreads();

    float acc = b3[t];
#pragma unroll 8
    for (int k = 0; k < HID; k++) acc += mean[k] * W3[k * HID + t];
    y[t] = fmaxf(acc, 0.0f);
    __syncthreads();

    if (t < OUT_DIM) {
        float acc2 = b4[t];
#pragma unroll 8
        for (int k = 0; k < HID; k++) acc2 += y[k] * W4[k * OUT_DIM + t];
        out[b * OUT_DIM + t] = acc2;
    }
}

// ---------------- launch: kernel launches ONLY ----------------
extern "C" void kernel_launch(void* const* d_in, const int* in_sizes, int n_in,
                              void* d_out, int out_size) {
    const float* x     = (const float*)d_in[0];
    const int*   ei    = (const int*)d_in[1];    // int32 (jax x64 disabled)
    const int*   batch = (const int*)d_in[2];
    const float* W1 = (const float*)d_in[3];
    const float* b1 = (const float*)d_in[4];
    const float* W2 = (const float*)d_in[5];
    const float* b2 = (const float*)d_in[6];
    const float* W3 = (const float*)d_in[7];
    const float* b3 = (const float*)d_in[8];
    const float* W4 = (const float*)d_in[9];
    const float* b4 = (const float*)d_in[10];
    float* out = (float*)d_out;

    const int* src = ei;
    const int* dst = ei + N_EDGES;

    // norm + CSR build
    k_zero<<<(N_NODES + 255) / 256, 256>>>();
    k_deg<<<(N_EDGES + 255) / 256, 256>>>(dst);
    k_dis<<<(N_NODES + 255) / 256, 256>>>();
    k_scan_part<<<SCAN_BLOCKS, 256>>>();
    k_scan_top<<<1, 256>>>();
    k_scan_add<<<(N_NODES + 255) / 256, 256>>>();
    k_fill<<<(N_EDGES + 255) / 256, 256>>>(src, dst);

    // layer 1: aggregate X (64 cols) via CSR gather, then GEMM -> bufA
    k_gather64<<<(N_NODES * 32 + 255) / 256, 256>>>(x);
    k_gemm_bias_relu<IN_DIM><<<(N_NODES + 63) / 64, 128>>>(W1, b1);

    // layer 2: aggregate bufA (128 cols) via CSR gather -> bufB, then GEMM -> bufA
    k_gather128<<<(N_NODES * 32 + 255) / 256, 256>>>();
    k_gemm_bias_relu<HID><<<(N_NODES + 63) / 64, 128>>>(W2, b2);

    // pool + head
    k_pool<<<(N_NODES * 32 + 255) / 256, 256>>>(batch);
    k_head<<<NB, 128>>>(W3, b3, W4, b4, out);
}